// round 1
// baseline (speedup 1.0000x reference)
#include <cuda_runtime.h>
#include <cstdint>

#define B_   16
#define F_   256
#define T_   4096
#define L_   128
#define M_   1024
#define D_   128
#define TC_  2048
#define N_   32768          // B*TC

#define OFF_VF  16777216    // B*F*T
#define OFF_IND 25165824    // OFF_VF + B*T*L

// Scratch (device globals — no allocation allowed)
__device__ __align__(16) float g_xqT[2][D_][N_];   // x permuted+transposed: [cb][d][n]
__device__ __align__(16) float g_eT[2][D_][M_];    // codebook transposed:   [cb][d][m]
__device__ __align__(16) float g_cm[2][M_];        // -5*||e_m||^2
__device__ __align__(16) int   g_idx[2][N_];       // argmax indices
__device__ __align__(16) float g_vf[B_ * T_ * L_]; // vq_feat [b][t][l]

// ---------- fp32x2 packed FMA helpers (FFMA2: only reachable via PTX) ----------
__device__ __forceinline__ unsigned long long pkdup(float x) {
    unsigned long long r; unsigned int xi = __float_as_uint(x);
    asm("mov.b64 %0, {%1, %2};" : "=l"(r) : "r"(xi), "r"(xi));
    return r;
}
__device__ __forceinline__ void ffma2(unsigned long long &acc, unsigned long long a,
                                      unsigned long long b) {
    asm("fma.rn.f32x2 %0, %1, %2, %0;" : "+l"(acc) : "l"(a), "l"(b));
}
__device__ __forceinline__ float2 upk(unsigned long long v) {
    unsigned int lo, hi;
    asm("mov.b64 {%0, %1}, %2;" : "=r"(lo), "=r"(hi) : "l"(v));
    float2 r; r.x = __uint_as_float(lo); r.y = __uint_as_float(hi);
    return r;
}

// ---------- Kernel 0: codebook transpose + (-5*||e||^2) ----------
__global__ void k_prep(const float* __restrict__ cb) {
    int i = blockIdx.y;
    int m = blockIdx.x * 128 + threadIdx.x;
    const float* row = cb + (size_t)(i * M_ + m) * D_;
    float s = 0.f;
#pragma unroll 8
    for (int d = 0; d < D_; d++) {
        float e = row[d];
        s += e * e;
        g_eT[i][d][m] = e;
    }
    g_cm[i][m] = -5.0f * s;
}

// ---------- Kernel 1: conv1x1_1 + VQ-layout permute -> g_xqT ----------
// x[b,t,l] = sum_f in[b,f,t] * w1[l,f];  g_xqT[l>>6][(t&1)*64 + (l&63)][b*TC + t/2] = x
__global__ void __launch_bounds__(256, 2) k_conv1(const float* __restrict__ in,
                                                  const float* __restrict__ w1) {
    __shared__ float sm[2 * 32 * 136];
    float* Aw = sm;               // [f][l]  (w1 chunk, transposed)
    float* Bi = sm + 32 * 136;    // [f][t]  (input chunk)
    int tid = threadIdx.x, tx = tid & 15, ty = tid >> 4;
    int b = blockIdx.y, t0 = blockIdx.x << 7;

    unsigned long long acc[8][4];   // rows a = l (ty*8+a), col pairs q over t (tx*8 + 2q{,+1})
#pragma unroll
    for (int a = 0; a < 8; a++)
#pragma unroll
        for (int q = 0; q < 4; q++) acc[a][q] = 0ULL;

    for (int kc = 0; kc < 8; kc++) {
        int f0 = kc << 5;
#pragma unroll
        for (int r = 0; r < 4; r++) {        // w1 chunk [128 l][32 f] -> Aw[f][l]
            int lin = tid + (r << 8);
            int l = lin >> 3, fq = (lin & 7) << 2;
            float4 v = *(const float4*)(w1 + l * F_ + f0 + fq);
            Aw[(fq + 0) * 136 + l] = v.x; Aw[(fq + 1) * 136 + l] = v.y;
            Aw[(fq + 2) * 136 + l] = v.z; Aw[(fq + 3) * 136 + l] = v.w;
        }
#pragma unroll
        for (int r = 0; r < 4; r++) {        // in chunk [32 f][128 t] -> Bi[f][t]
            int lin = tid + (r << 8);
            int f = lin >> 5, tq = (lin & 31) << 2;
            float4 v = *(const float4*)(in + (size_t)(b * F_ + f0 + f) * T_ + t0 + tq);
            *(float4*)(Bi + f * 136 + tq) = v;
        }
        __syncthreads();
#pragma unroll 8
        for (int f = 0; f < 32; f++) {
            float4 a0 = *(const float4*)(Aw + f * 136 + ty * 8);
            float4 a1 = *(const float4*)(Aw + f * 136 + ty * 8 + 4);
            const unsigned long long* bp =
                (const unsigned long long*)(Bi + f * 136 + tx * 8);
            unsigned long long b0 = bp[0], b1 = bp[1], b2 = bp[2], b3 = bp[3];
            unsigned long long ad[8] = {pkdup(a0.x), pkdup(a0.y), pkdup(a0.z), pkdup(a0.w),
                                        pkdup(a1.x), pkdup(a1.y), pkdup(a1.z), pkdup(a1.w)};
#pragma unroll
            for (int a = 0; a < 8; a++) {
                ffma2(acc[a][0], ad[a], b0);
                ffma2(acc[a][1], ad[a], b1);
                ffma2(acc[a][2], ad[a], b2);
                ffma2(acc[a][3], ad[a], b3);
            }
        }
        __syncthreads();
    }

    // Stage through smem (two halves to fit) and write coalesced into g_xqT
    int nb = b * TC_ + (t0 >> 1);
    for (int h = 0; h < 2; h++) {
        if ((tx >> 3) == h) {
#pragma unroll
            for (int a = 0; a < 8; a++)
#pragma unroll
                for (int q = 0; q < 4; q++) {
                    float2 s = upk(acc[a][q]);
                    int tl = ((tx & 7) << 3) + (q << 1);   // local t within half
                    sm[tl * 129 + ty * 8 + a] = s.x;
                    sm[(tl + 1) * 129 + ty * 8 + a] = s.y;
                }
        }
        __syncthreads();
#pragma unroll
        for (int w = 0; w < 32; w++) {
            int e = (w << 8) + tid;          // 8192 elements per half
            int nn = e & 31, rem = e >> 5;
            int cf = rem & 1, l = rem >> 1;
            float v = sm[(2 * nn + cf) * 129 + l];
            int ci = l >> 6, d = (cf << 6) + (l & 63);
            g_xqT[ci][d][nb + h * 32 + nn] = v;
        }
        __syncthreads();
    }
}

// ---------- Kernel 2: distance GEMM + gumbel + row argmax ----------
// score(n,m) = 10*(x_n . e_m) - 5*||e_m||^2 + gumbel[n,m]   (monotone == reference logits+g)
__global__ void __launch_bounds__(256, 2) k_dist(const float* __restrict__ gum) {
    __shared__ float sm[2 * 32 * 136];
    float* Xs = sm;               // [d][n]
    float* Es = sm + 32 * 136;    // [d][m]
    int tid = threadIdx.x, tx = tid & 15, ty = tid >> 4;
    int i = blockIdx.y;
    int nb = blockIdx.x << 7;     // 128 rows per block

    float bestv[8]; int bestm[8];
#pragma unroll
    for (int a = 0; a < 8; a++) { bestv[a] = -3.4e38f; bestm[a] = 0; }

    for (int mc = 0; mc < 8; mc++) {
        int m0 = mc << 7;
        unsigned long long acc[8][4];  // rows a over n (ty*8+a), pairs q over m (tx*8+2q{,+1})
#pragma unroll
        for (int a = 0; a < 8; a++)
#pragma unroll
            for (int q = 0; q < 4; q++) acc[a][q] = 0ULL;

        for (int dc = 0; dc < 4; dc++) {
            int d0 = dc << 5;
#pragma unroll
            for (int r = 0; r < 4; r++) {
                int lin = tid + (r << 8);
                int dd = lin >> 5, rq = (lin & 31) << 2;
                *(float4*)(Xs + dd * 136 + rq) =
                    *(const float4*)(&g_xqT[i][d0 + dd][nb + rq]);
                *(float4*)(Es + dd * 136 + rq) =
                    *(const float4*)(&g_eT[i][d0 + dd][m0 + rq]);
            }
            __syncthreads();
#pragma unroll 8
            for (int dd = 0; dd < 32; dd++) {
                float4 a0 = *(const float4*)(Xs + dd * 136 + ty * 8);
                float4 a1 = *(const float4*)(Xs + dd * 136 + ty * 8 + 4);
                const unsigned long long* bp =
                    (const unsigned long long*)(Es + dd * 136 + tx * 8);
                unsigned long long b0 = bp[0], b1 = bp[1], b2 = bp[2], b3 = bp[3];
                unsigned long long ad[8] = {pkdup(a0.x), pkdup(a0.y), pkdup(a0.z), pkdup(a0.w),
                                            pkdup(a1.x), pkdup(a1.y), pkdup(a1.z), pkdup(a1.w)};
#pragma unroll
                for (int a = 0; a < 8; a++) {
                    ffma2(acc[a][0], ad[a], b0);
                    ffma2(acc[a][1], ad[a], b1);
                    ffma2(acc[a][2], ad[a], b2);
                    ffma2(acc[a][3], ad[a], b3);
                }
            }
            __syncthreads();
        }

        // epilogue: add -5||e||^2 + gumbel, update running argmax
        float4 c0 = *(const float4*)(&g_cm[i][m0 + tx * 8]);
        float4 c1 = *(const float4*)(&g_cm[i][m0 + tx * 8 + 4]);
#pragma unroll
        for (int a = 0; a < 8; a++) {
            const float* gp = gum + ((size_t)i * N_ + nb + ty * 8 + a) * (size_t)M_
                              + m0 + tx * 8;
            float4 g0 = *(const float4*)gp;
            float4 g1 = *(const float4*)(gp + 4);
            float2 s0 = upk(acc[a][0]), s1 = upk(acc[a][1]);
            float2 s2 = upk(acc[a][2]), s3 = upk(acc[a][3]);
            float sc[8] = {10.f * s0.x + c0.x + g0.x, 10.f * s0.y + c0.y + g0.y,
                           10.f * s1.x + c0.z + g0.z, 10.f * s1.y + c0.w + g0.w,
                           10.f * s2.x + c1.x + g1.x, 10.f * s2.y + c1.y + g1.y,
                           10.f * s3.x + c1.z + g1.z, 10.f * s3.y + c1.w + g1.w};
#pragma unroll
            for (int cc = 0; cc < 8; cc++) {
                int m = m0 + tx * 8 + cc;
                if (sc[cc] > bestv[a]) { bestv[a] = sc[cc]; bestm[a] = m; }
            }
        }
    }

    // reduce across the 16 tx lanes (half-warp), keep lowest m on ties
#pragma unroll
    for (int a = 0; a < 8; a++) {
        float v = bestv[a]; int m = bestm[a];
#pragma unroll
        for (int off = 8; off >= 1; off >>= 1) {
            float ov = __shfl_down_sync(0xffffffffu, v, off, 16);
            int   om = __shfl_down_sync(0xffffffffu, m, off, 16);
            if (ov > v || (ov == v && om < m)) { v = ov; m = om; }
        }
        if (tx == 0) g_idx[i][nb + ty * 8 + a] = m;
    }
}

// ---------- Kernel 3: dequantize gather -> g_vf (+ optional d_out vf/inds) ----------
__global__ void k_gather(const float* __restrict__ cb, float* __restrict__ dout,
                         int write_vf, int write_inds) {
    int gt = blockIdx.x * 256 + threadIdx.x;  // 0..2097151  (float4 index of vq_feat)
    int l4 = gt & 31;
    int t = (gt >> 5) & 4095;
    int b = gt >> 17;
    int l = l4 << 2;
    int ci = l >> 6;
    int cf = t & 1;
    int n = b * TC_ + (t >> 1);
    int idx = g_idx[ci][n];
    float4 v = *(const float4*)(cb + (size_t)(ci * M_ + idx) * D_ + (cf << 6) + (l & 63));
    *(float4*)(g_vf + ((size_t)gt << 2)) = v;
    if (write_vf) *(float4*)(dout + OFF_VF + ((size_t)gt << 2)) = v;
    if (write_inds && gt < 65536) {
        int ii = gt & 1, nn = gt >> 1;   // quant_inds[b][tc][k] = [n][k]
        dout[OFF_IND + gt] = (float)g_idx[ii][nn];
    }
}

// ---------- Kernel 4: conv1x1_2 -> out[b][f][t] ----------
__global__ void __launch_bounds__(256, 2) k_conv2(const float* __restrict__ w2,
                                                  float* __restrict__ dout) {
    __shared__ float sm[2 * 32 * 136];
    float* Ws = sm;               // [l][f]
    float* Vs = sm + 32 * 136;    // [l][t]
    int tid = threadIdx.x, tx = tid & 15, ty = tid >> 4;
    int t0 = blockIdx.x << 7;
    int f0 = blockIdx.y << 7;
    int b = blockIdx.z;

    unsigned long long acc[8][4];  // rows a over f, pairs q over t
#pragma unroll
    for (int a = 0; a < 8; a++)
#pragma unroll
        for (int q = 0; q < 4; q++) acc[a][q] = 0ULL;

    for (int lc = 0; lc < 4; lc++) {
        int l0 = lc << 5;
#pragma unroll
        for (int r = 0; r < 4; r++) {
            int lin = tid + (r << 8);
            int ff = lin >> 3, lq = (lin & 7) << 2;
            float4 v = *(const float4*)(w2 + (f0 + ff) * D_ + l0 + lq);
            Ws[(lq + 0) * 136 + ff] = v.x; Ws[(lq + 1) * 136 + ff] = v.y;
            Ws[(lq + 2) * 136 + ff] = v.z; Ws[(lq + 3) * 136 + ff] = v.w;
            int tt = ff;  // same decomposition for vf tile
            float4 u = *(const float4*)(g_vf + (size_t)(b * T_ + t0 + tt) * L_ + l0 + lq);
            Vs[(lq + 0) * 136 + tt] = u.x; Vs[(lq + 1) * 136 + tt] = u.y;
            Vs[(lq + 2) * 136 + tt] = u.z; Vs[(lq + 3) * 136 + tt] = u.w;
        }
        __syncthreads();
#pragma unroll 8
        for (int lw = 0; lw < 32; lw++) {
            float4 a0 = *(const float4*)(Ws + lw * 136 + ty * 8);
            float4 a1 = *(const float4*)(Ws + lw * 136 + ty * 8 + 4);
            const unsigned long long* bp =
                (const unsigned long long*)(Vs + lw * 136 + tx * 8);
            unsigned long long b0 = bp[0], b1 = bp[1], b2 = bp[2], b3 = bp[3];
            unsigned long long ad[8] = {pkdup(a0.x), pkdup(a0.y), pkdup(a0.z), pkdup(a0.w),
                                        pkdup(a1.x), pkdup(a1.y), pkdup(a1.z), pkdup(a1.w)};
#pragma unroll
            for (int a = 0; a < 8; a++) {
                ffma2(acc[a][0], ad[a], b0);
                ffma2(acc[a][1], ad[a], b1);
                ffma2(acc[a][2], ad[a], b2);
                ffma2(acc[a][3], ad[a], b3);
            }
        }
        __syncthreads();
    }

#pragma unroll
    for (int a = 0; a < 8; a++) {
        float2 s0 = upk(acc[a][0]), s1 = upk(acc[a][1]);
        float2 s2 = upk(acc[a][2]), s3 = upk(acc[a][3]);
        float4 o0 = make_float4(s0.x, s0.y, s1.x, s1.y);
        float4 o1 = make_float4(s2.x, s2.y, s3.x, s3.y);
        size_t base = (size_t)(b * F_ + f0 + ty * 8 + a) * T_ + t0 + tx * 8;
        *(float4*)(dout + base) = o0;
        *(float4*)(dout + base + 4) = o1;
    }
}

extern "C" void kernel_launch(void* const* d_in, const int* in_sizes, int n_in,
                              void* d_out, int out_size) {
    const float* in  = (const float*)d_in[0];   // [16,256,4096,1]
    const float* w1  = (const float*)d_in[1];   // [128,256]
    const float* w2  = (const float*)d_in[2];   // [256,128]
    const float* cb  = (const float*)d_in[3];   // [2,1024,128]
    const float* gum = (const float*)d_in[4];   // [2,32768,1024]
    float* dout = (float*)d_out;

    int write_vf   = (out_size >= OFF_VF + B_ * T_ * L_) ? 1 : 0;
    int write_inds = (out_size >= OFF_IND + N_ * 2) ? 1 : 0;

    k_prep<<<dim3(8, 2), 128>>>(cb);
    k_conv1<<<dim3(32, 16), 256>>>(in, w1);
    k_dist<<<dim3(256, 2), 256>>>(gum);
    k_gather<<<8192, 256>>>(cb, dout, write_vf, write_inds);
    k_conv2<<<dim3(32, 2, 16), 256>>>(w2, dout);
}